// round 2
// baseline (speedup 1.0000x reference)
#include <cuda_runtime.h>
#include <cuda_bf16.h>
#include <math.h>

// Problem constants
#define Bq    1
#define CIN   256
#define COUT  128
#define Hh    64
#define Ww    192
#define HW    (Hh*Ww)          // 12288
#define Hp    (Hh+2)           // 66
#define Wp    (Ww+2)           // 194
#define Pp    (Hp*Wp)          // 12804
#define TAPS  36               // 9 taps x 4 gathers
#define EPSv  1e-5f
#define LEAK  0.01f

// ---------------- scratch (static __device__ — no allocation) ----------------
__device__ int   g_tidx[TAPS * HW];      // gather indices into UNPADDED x, tap-major
__device__ float g_tw[TAPS * HW];        // gather weights (0 where tap hits pad ring)
__device__ float g_y0[CIN * HW];         // deformable-gather output (12.6 MB)
__device__ float g_t1[COUT * HW];
__device__ float g_t2[COUT * HW];
__device__ float g_t3[COUT * HW];
__device__ float g_scale[COUT];
__device__ float g_bias[COUT];

// ---------------- 1) per-pixel gather tables ----------------
// Converts each clamped flat padded index to an unpadded index; taps landing on
// the zero pad ring get weight 0 (value there is 0, so contribution is 0).
__device__ __forceinline__ void emit_tap(int slot, int p, float av_padded, float w) {
    int id = (int)av_padded;          // 0 .. Pp-1
    int r  = id / Wp;
    int cc = id - r * Wp;
    int idx = 0;
    if (r >= 1 && r <= Hh && cc >= 1 && cc <= Ww)
        idx = (r - 1) * Ww + (cc - 1);
    else
        w = 0.f;
    g_tidx[slot * HW + p] = idx;
    g_tw[slot * HW + p]   = w;
}

__global__ void tab_kernel(const float* __restrict__ xr) {
    int p = blockIdx.x * 256 + threadIdx.x;
    if (p >= HW) return;
    float off = 3.0f * (1.0f / (1.0f + expf(-xr[p])));
    int r = p / Ww, cc = p - r * Ww;
    float v0 = (float)((r + 1) * Wp + (cc + 1));
    const float xo9[9] = {-1,0,1,-1,0,1,-1,0,1};
    const float yo9[9] = {-1,-1,-1,0,0,0,1,1,1};
    const float Pm1 = (float)(Pp - 1);
    const float Wpf = (float)Wp;
    #pragma unroll
    for (int k = 0; k < 9; k++) {
        float xo = xo9[k], yo = yo9[k];
        float pre  = v0 + xo + yo * Wpf;                       // exact ints in fp32
        float offv = __fadd_rn(__fmul_rn(off, xo), yo * Wpf);  // match mul-then-add
        float after = __fadd_rn(pre, offv);
        float avf  = fminf(fmaxf(pre + floorf(offv), 0.f), Pm1);
        float avf1 = fminf(fmaxf(avf + xo, 0.f), Pm1);
        float avc  = fminf(fmaxf(pre + ceilf(offv), 0.f), Pm1);
        float avc1 = fminf(fmaxf(avc + xo, 0.f), Pm1);
        float g1w = fabsf((after - avf)  / Wpf);
        float g2w = fabsf((avc1 - after) / Wpf);
        float wf  = fabsf(after - avf);
        float wf1 = fabsf(avf1 - after);
        float wc1 = fabsf(after - avc1);
        float wc  = fabsf(avc  - after);
        int t = k * 4;
        emit_tap(t + 0, p, avf,  g1w * wf);
        emit_tap(t + 1, p, avf1, g1w * wf1);
        emit_tap(t + 2, p, avc1, g2w * wc1);
        emit_tap(t + 3, p, avc,  g2w * wc);
    }
}

// ---------------- 2) deformable gather-contraction ----------------
// block: 64 pixels x 64 channels, 256 threads (64 px x 4 channel groups)
__global__ void gather_kernel(const float* __restrict__ x,
                              const float* __restrict__ ro /* (CIN,9) */) {
    __shared__ int   s_idx[TAPS * 64];
    __shared__ float s_w[TAPS * 64];
    __shared__ float s_ro[64 * 9];
    int p0 = blockIdx.x * 64;
    int c0 = blockIdx.y * 64;
    int tid = threadIdx.x;
    for (int i = tid; i < TAPS * 64; i += 256) {
        int t = i >> 6, px = i & 63;
        s_idx[i] = g_tidx[t * HW + p0 + px];
        s_w[i]   = g_tw[t * HW + p0 + px];
    }
    for (int i = tid; i < 64 * 9; i += 256) {
        int cl = i / 9, k = i - cl * 9;
        s_ro[i] = ro[(c0 + cl) * 9 + k];
    }
    __syncthreads();
    int px = tid & 63;
    int cg = tid >> 6;
    int p = p0 + px;
    #pragma unroll 1
    for (int ci = 0; ci < 16; ci++) {
        int cl = cg * 16 + ci;
        int c  = c0 + cl;
        const float* xp = x + (size_t)c * HW;
        float acc = 0.f;
        #pragma unroll
        for (int k = 0; k < 9; k++) {
            float rk = s_ro[cl * 9 + k];
            #pragma unroll
            for (int j = 0; j < 4; j++) {
                int t = k * 4 + j;
                int id = s_idx[t * 64 + px];
                float wv = s_w[t * 64 + px];
                acc = fmaf(wv * rk, __ldg(xp + id), acc);
            }
        }
        g_y0[(size_t)c * HW + p] = acc;
    }
}

// ---------------- 3) fp32 GEMM: C[128,N] = A[128,K] * B[K,N] ----------------
// 64x64 tile, BK=16, 256 threads, 4x4 microtile
__global__ void gemm_kernel(const float* __restrict__ A, const float* __restrict__ B,
                            float* __restrict__ C, int K) {
    __shared__ float As[16][65];
    __shared__ float Bs[16][64];
    const int N = HW;
    int bn = blockIdx.x * 64, bm = blockIdx.y * 64;
    int tid = threadIdx.x;
    int tx = tid & 15, ty = tid >> 4;
    float acc[4][4] = {};
    for (int k0 = 0; k0 < K; k0 += 16) {
        {
            int m  = tid >> 2;
            int kk = (tid & 3) * 4;
            float4 av = *(const float4*)&A[(size_t)(bm + m) * K + k0 + kk];
            As[kk + 0][m] = av.x; As[kk + 1][m] = av.y;
            As[kk + 2][m] = av.z; As[kk + 3][m] = av.w;
        }
        {
            int kk = tid >> 4;
            int n  = (tid & 15) * 4;
            *(float4*)&Bs[kk][n] = *(const float4*)&B[(size_t)(k0 + kk) * N + bn + n];
        }
        __syncthreads();
        #pragma unroll
        for (int k = 0; k < 16; k++) {
            float a[4], b[4];
            #pragma unroll
            for (int i = 0; i < 4; i++) a[i] = As[k][ty * 4 + i];
            #pragma unroll
            for (int j = 0; j < 4; j++) b[j] = Bs[k][tx * 4 + j];
            #pragma unroll
            for (int i = 0; i < 4; i++)
                #pragma unroll
                for (int j = 0; j < 4; j++)
                    acc[i][j] = fmaf(a[i], b[j], acc[i][j]);
        }
        __syncthreads();
    }
    #pragma unroll
    for (int i = 0; i < 4; i++) {
        float4 v = make_float4(acc[i][0], acc[i][1], acc[i][2], acc[i][3]);
        *(float4*)&C[(size_t)(bm + ty * 4 + i) * N + bn + tx * 4] = v;
    }
}

// ---------------- 4) per-channel BN stats -> fused scale/bias ----------------
__global__ void stats_kernel(const float* __restrict__ t,
                             const float* __restrict__ g, const float* __restrict__ b) {
    __shared__ float ss[256], ss2[256];
    int c = blockIdx.x;
    float s = 0.f, s2 = 0.f;
    for (int i = threadIdx.x; i < HW; i += 256) {
        float v = t[(size_t)c * HW + i];
        s += v; s2 = fmaf(v, v, s2);
    }
    ss[threadIdx.x] = s; ss2[threadIdx.x] = s2;
    __syncthreads();
    for (int ofs = 128; ofs > 0; ofs >>= 1) {
        if (threadIdx.x < ofs) {
            ss[threadIdx.x]  += ss[threadIdx.x + ofs];
            ss2[threadIdx.x] += ss2[threadIdx.x + ofs];
        }
        __syncthreads();
    }
    if (threadIdx.x == 0) {
        float mean = ss[0] / (float)HW;
        float var  = ss2[0] / (float)HW - mean * mean;
        float rstd = rsqrtf(var + EPSv);
        float sc = g[c] * rstd;
        g_scale[c] = sc;
        g_bias[c]  = b[c] - mean * sc;
    }
}

__device__ __forceinline__ float bn_leaky(float v, float sc, float bi) {
    float y = fmaf(v, sc, bi);
    return y >= 0.f ? y : LEAK * y;
}

// ---------------- 5) depthwise 3x3 with fused BN+leaky on input ----------------
__global__ void dw_kernel(const float* __restrict__ in, const float* __restrict__ dw,
                          float* __restrict__ out) {
    int c = blockIdx.y;
    int p = blockIdx.x * 256 + threadIdx.x;
    if (p >= HW) return;
    int r = p / Ww, col = p - r * Ww;
    float sc = g_scale[c], bi = g_bias[c];
    float wl[9];
    #pragma unroll
    for (int i = 0; i < 9; i++) wl[i] = dw[c * 9 + i];
    const float* ip = in + (size_t)c * HW;
    float acc = 0.f;
    #pragma unroll
    for (int dy = -1; dy <= 1; dy++) {
        int rr = r + dy;
        if (rr < 0 || rr >= Hh) continue;
        #pragma unroll
        for (int dx = -1; dx <= 1; dx++) {
            int cc = col + dx;
            if (cc < 0 || cc >= Ww) continue;
            float v = bn_leaky(ip[rr * Ww + cc], sc, bi);
            acc = fmaf(v, wl[(dy + 1) * 3 + (dx + 1)], acc);
        }
    }
    out[(size_t)c * HW + p] = acc;
}

// ---------------- 6) final BN+leaky apply ----------------
__global__ void apply_kernel(const float* __restrict__ in, float* __restrict__ out) {
    int i = blockIdx.x * 256 + threadIdx.x;
    if (i >= COUT * HW) return;
    int c = i / HW;
    out[i] = bn_leaky(in[i], g_scale[c], g_bias[c]);
}

// ---------------- launch ----------------
extern "C" void kernel_launch(void* const* d_in, const int* in_sizes, int n_in,
                              void* d_out, int out_size) {
    const float* x        = (const float*)d_in[0];
    const float* x_range  = (const float*)d_in[1];
    const float* range_o  = (const float*)d_in[2];
    const float* w_reduce = (const float*)d_in[3];
    const float* g_r      = (const float*)d_in[4];
    const float* b_r      = (const float*)d_in[5];
    const float* dw1      = (const float*)d_in[6];
    const float* pw1      = (const float*)d_in[7];
    const float* g1       = (const float*)d_in[8];
    const float* b1       = (const float*)d_in[9];
    const float* dw2      = (const float*)d_in[10];
    const float* pw2      = (const float*)d_in[11];
    const float* g2       = (const float*)d_in[12];
    const float* b2       = (const float*)d_in[13];
    float* out = (float*)d_out;

    float *t1, *t2, *t3, *y0;
    cudaGetSymbolAddress((void**)&t1, g_t1);
    cudaGetSymbolAddress((void**)&t2, g_t2);
    cudaGetSymbolAddress((void**)&t3, g_t3);
    cudaGetSymbolAddress((void**)&y0, g_y0);

    tab_kernel<<<(HW + 255) / 256, 256>>>(x_range);
    gather_kernel<<<dim3(HW / 64, CIN / 64), 256>>>(x, range_o);

    gemm_kernel<<<dim3(HW / 64, COUT / 64), 256>>>(w_reduce, y0, t1, CIN);
    stats_kernel<<<COUT, 256>>>(t1, g_r, b_r);
    dw_kernel<<<dim3((HW + 255) / 256, COUT), 256>>>(t1, dw1, t2);

    gemm_kernel<<<dim3(HW / 64, COUT / 64), 256>>>(pw1, t2, t3, COUT);
    stats_kernel<<<COUT, 256>>>(t3, g1, b1);
    dw_kernel<<<dim3((HW + 255) / 256, COUT), 256>>>(t3, dw2, t2);

    gemm_kernel<<<dim3(HW / 64, COUT / 64), 256>>>(pw2, t2, t1, COUT);
    stats_kernel<<<COUT, 256>>>(t1, g2, b2);
    apply_kernel<<<(COUT * HW + 255) / 256, 256>>>(t1, out);
}

// round 3
// speedup vs baseline: 1.0763x; 1.0763x over previous
#include <cuda_runtime.h>
#include <cuda_bf16.h>
#include <math.h>

// Problem constants
#define Bq    1
#define CIN   256
#define COUT  128
#define Hh    64
#define Ww    192
#define HW    (Hh*Ww)          // 12288
#define Hp    (Hh+2)           // 66
#define Wp    (Ww+2)           // 194
#define Pp    (Hp*Wp)          // 12804
#define TAPS  36               // 9 taps x 4 gathers
#define EPSv  1e-5f
#define LEAK  0.01f

// ---------------- scratch (static __device__ — no allocation) ----------------
__device__ int   g_tidx[TAPS * HW];      // gather indices into UNPADDED x, tap-major
__device__ float g_tw[TAPS * HW];        // gather weights (0 where tap hits pad ring)
__device__ float g_y0[CIN * HW];         // deformable-gather output (12.6 MB)
__device__ float g_t1[COUT * HW];
__device__ float g_t2[COUT * HW];
__device__ float g_t3[COUT * HW];
__device__ float g_sum[3][COUT];         // per-stage channel sums
__device__ float g_sum2[3][COUT];        // per-stage channel sum-of-squares

// ---------------- 0) zero the stat accumulators ----------------
__global__ void init_kernel() {
    int i = threadIdx.x;
    if (i < COUT) {
        #pragma unroll
        for (int s = 0; s < 3; s++) { g_sum[s][i] = 0.f; g_sum2[s][i] = 0.f; }
    }
}

// ---------------- 1) per-pixel gather tables ----------------
// Converts each clamped flat padded index to an unpadded index; taps landing on
// the zero pad ring get weight 0 (value there is 0, so contribution is 0).
__device__ __forceinline__ void emit_tap(int slot, int p, float av_padded, float w) {
    int id = (int)av_padded;          // 0 .. Pp-1
    int r  = id / Wp;
    int cc = id - r * Wp;
    int idx = 0;
    if (r >= 1 && r <= Hh && cc >= 1 && cc <= Ww)
        idx = (r - 1) * Ww + (cc - 1);
    else
        w = 0.f;
    g_tidx[slot * HW + p] = idx;
    g_tw[slot * HW + p]   = w;
}

__global__ void tab_kernel(const float* __restrict__ xr) {
    int p = blockIdx.x * 256 + threadIdx.x;
    if (p >= HW) return;
    float off = 3.0f * (1.0f / (1.0f + expf(-xr[p])));
    int r = p / Ww, cc = p - r * Ww;
    float v0 = (float)((r + 1) * Wp + (cc + 1));
    const float xo9[9] = {-1,0,1,-1,0,1,-1,0,1};
    const float yo9[9] = {-1,-1,-1,0,0,0,1,1,1};
    const float Pm1 = (float)(Pp - 1);
    const float Wpf = (float)Wp;
    #pragma unroll
    for (int k = 0; k < 9; k++) {
        float xo = xo9[k], yo = yo9[k];
        float pre  = v0 + xo + yo * Wpf;                       // exact ints in fp32
        float offv = __fadd_rn(__fmul_rn(off, xo), yo * Wpf);  // match mul-then-add
        float after = __fadd_rn(pre, offv);
        float avf  = fminf(fmaxf(pre + floorf(offv), 0.f), Pm1);
        float avf1 = fminf(fmaxf(avf + xo, 0.f), Pm1);
        float avc  = fminf(fmaxf(pre + ceilf(offv), 0.f), Pm1);
        float avc1 = fminf(fmaxf(avc + xo, 0.f), Pm1);
        float g1w = fabsf((after - avf)  / Wpf);
        float g2w = fabsf((avc1 - after) / Wpf);
        float wf  = fabsf(after - avf);
        float wf1 = fabsf(avf1 - after);
        float wc1 = fabsf(after - avc1);
        float wc  = fabsf(avc  - after);
        int t = k * 4;
        emit_tap(t + 0, p, avf,  g1w * wf);
        emit_tap(t + 1, p, avf1, g1w * wf1);
        emit_tap(t + 2, p, avc1, g2w * wc1);
        emit_tap(t + 3, p, avc,  g2w * wc);
    }
}

// ---------------- 2) deformable gather-contraction ----------------
// block: 64 pixels x 64 channels, 256 threads (64 px x 4 channel groups)
__global__ void gather_kernel(const float* __restrict__ x,
                              const float* __restrict__ ro /* (CIN,9) */) {
    __shared__ int   s_idx[TAPS * 64];
    __shared__ float s_w[TAPS * 64];
    __shared__ float s_ro[64 * 9];
    int p0 = blockIdx.x * 64;
    int c0 = blockIdx.y * 64;
    int tid = threadIdx.x;
    for (int i = tid; i < TAPS * 64; i += 256) {
        int t = i >> 6, px = i & 63;
        s_idx[i] = g_tidx[t * HW + p0 + px];
        s_w[i]   = g_tw[t * HW + p0 + px];
    }
    for (int i = tid; i < 64 * 9; i += 256) {
        int cl = i / 9, k = i - cl * 9;
        s_ro[i] = ro[(c0 + cl) * 9 + k];
    }
    __syncthreads();
    int px = tid & 63;
    int cg = tid >> 6;
    int p = p0 + px;
    #pragma unroll 1
    for (int ci = 0; ci < 16; ci++) {
        int cl = cg * 16 + ci;
        int c  = c0 + cl;
        const float* xp = x + (size_t)c * HW;
        float acc = 0.f;
        #pragma unroll
        for (int k = 0; k < 9; k++) {
            float rk = s_ro[cl * 9 + k];
            #pragma unroll
            for (int j = 0; j < 4; j++) {
                int t = k * 4 + j;
                int id = s_idx[t * 64 + px];
                float wv = s_w[t * 64 + px];
                acc = fmaf(wv * rk, __ldg(xp + id), acc);
            }
        }
        g_y0[(size_t)c * HW + p] = acc;
    }
}

// ---------------- 3) fp32 GEMM + fused BN-stat epilogue ----------------
// C[128,N] = A[128,K] * B[K,N]; 64x64 tile, BK=16, 256 threads, 4x4 microtile.
// Epilogue: per-channel partial sum / sum-sq -> atomicAdd into g_sum/g_sum2.
__global__ void gemm_kernel(const float* __restrict__ A, const float* __restrict__ B,
                            float* __restrict__ C, int K,
                            float* __restrict__ sum, float* __restrict__ sum2) {
    __shared__ float As[16][68];    // 68: keeps As[k][4*ty] 16B-aligned
    __shared__ float Bs[16][64];
    const int N = HW;
    int bn = blockIdx.x * 64, bm = blockIdx.y * 64;
    int tid = threadIdx.x;
    int tx = tid & 15, ty = tid >> 4;
    float acc[4][4] = {};
    for (int k0 = 0; k0 < K; k0 += 16) {
        {
            int m  = tid >> 2;
            int kk = (tid & 3) * 4;
            float4 av = *(const float4*)&A[(size_t)(bm + m) * K + k0 + kk];
            As[kk + 0][m] = av.x; As[kk + 1][m] = av.y;
            As[kk + 2][m] = av.z; As[kk + 3][m] = av.w;
        }
        {
            int kk = tid >> 4;
            int n  = (tid & 15) * 4;
            *(float4*)&Bs[kk][n] = *(const float4*)&B[(size_t)(k0 + kk) * N + bn + n];
        }
        __syncthreads();
        #pragma unroll
        for (int k = 0; k < 16; k++) {
            float4 a4 = *(const float4*)&As[k][ty * 4];
            float4 b4 = *(const float4*)&Bs[k][tx * 4];
            float a[4] = {a4.x, a4.y, a4.z, a4.w};
            float b[4] = {b4.x, b4.y, b4.z, b4.w};
            #pragma unroll
            for (int i = 0; i < 4; i++)
                #pragma unroll
                for (int j = 0; j < 4; j++)
                    acc[i][j] = fmaf(a[i], b[j], acc[i][j]);
        }
        __syncthreads();
    }
    #pragma unroll
    for (int i = 0; i < 4; i++) {
        float4 v = make_float4(acc[i][0], acc[i][1], acc[i][2], acc[i][3]);
        *(float4*)&C[(size_t)(bm + ty * 4 + i) * N + bn + tx * 4] = v;
    }
    // ---- fused BN stat partials ----
    #pragma unroll
    for (int i = 0; i < 4; i++) {
        float s  = acc[i][0] + acc[i][1] + acc[i][2] + acc[i][3];
        float s2 = fmaf(acc[i][0], acc[i][0],
                   fmaf(acc[i][1], acc[i][1],
                   fmaf(acc[i][2], acc[i][2], acc[i][3] * acc[i][3])));
        #pragma unroll
        for (int off = 8; off > 0; off >>= 1) {
            s  += __shfl_down_sync(0xffffffffu, s,  off, 16);
            s2 += __shfl_down_sync(0xffffffffu, s2, off, 16);
        }
        if (tx == 0) {
            int c = bm + ty * 4 + i;
            atomicAdd(&sum[c],  s);
            atomicAdd(&sum2[c], s2);
        }
    }
}

// ---------------- BN scale/bias from accumulated stats ----------------
__device__ __forceinline__ void bn_coeffs(int c, const float* sum, const float* sum2,
                                          const float* __restrict__ g,
                                          const float* __restrict__ b,
                                          float& sc, float& bi) {
    float mean = sum[c] * (1.f / (float)HW);
    float var  = sum2[c] * (1.f / (float)HW) - mean * mean;
    float rstd = rsqrtf(var + EPSv);
    sc = g[c] * rstd;
    bi = b[c] - mean * sc;
}

__device__ __forceinline__ float bn_leaky(float v, float sc, float bi) {
    float y = fmaf(v, sc, bi);
    return y >= 0.f ? y : LEAK * y;
}

// ---------------- 4) depthwise 3x3 with fused BN+leaky on input ----------------
__global__ void dw_kernel(const float* __restrict__ in, const float* __restrict__ dw,
                          float* __restrict__ out,
                          const float* __restrict__ sum, const float* __restrict__ sum2,
                          const float* __restrict__ g, const float* __restrict__ b) {
    int c = blockIdx.y;
    int p = blockIdx.x * 256 + threadIdx.x;
    if (p >= HW) return;
    int r = p / Ww, col = p - r * Ww;
    float sc, bi;
    bn_coeffs(c, sum, sum2, g, b, sc, bi);
    float wl[9];
    #pragma unroll
    for (int i = 0; i < 9; i++) wl[i] = dw[c * 9 + i];
    const float* ip = in + (size_t)c * HW;
    float acc = 0.f;
    #pragma unroll
    for (int dy = -1; dy <= 1; dy++) {
        int rr = r + dy;
        if (rr < 0 || rr >= Hh) continue;
        #pragma unroll
        for (int dx = -1; dx <= 1; dx++) {
            int cc = col + dx;
            if (cc < 0 || cc >= Ww) continue;
            float v = bn_leaky(ip[rr * Ww + cc], sc, bi);
            acc = fmaf(v, wl[(dy + 1) * 3 + (dx + 1)], acc);
        }
    }
    out[(size_t)c * HW + p] = acc;
}

// ---------------- 5) final BN+leaky apply (vectorized) ----------------
__global__ void apply_kernel(const float* __restrict__ in, float* __restrict__ out,
                             const float* __restrict__ sum, const float* __restrict__ sum2,
                             const float* __restrict__ g, const float* __restrict__ b) {
    int i = blockIdx.x * 256 + threadIdx.x;       // float4 index
    if (i >= COUT * HW / 4) return;
    int c = (i * 4) / HW;                          // HW % 4 == 0 -> uniform in vec
    float sc, bi;
    bn_coeffs(c, sum, sum2, g, b, sc, bi);
    float4 v = ((const float4*)in)[i];
    v.x = bn_leaky(v.x, sc, bi);
    v.y = bn_leaky(v.y, sc, bi);
    v.z = bn_leaky(v.z, sc, bi);
    v.w = bn_leaky(v.w, sc, bi);
    ((float4*)out)[i] = v;
}

// ---------------- launch ----------------
extern "C" void kernel_launch(void* const* d_in, const int* in_sizes, int n_in,
                              void* d_out, int out_size) {
    const float* x        = (const float*)d_in[0];
    const float* x_range  = (const float*)d_in[1];
    const float* range_o  = (const float*)d_in[2];
    const float* w_reduce = (const float*)d_in[3];
    const float* g_r      = (const float*)d_in[4];
    const float* b_r      = (const float*)d_in[5];
    const float* dw1      = (const float*)d_in[6];
    const float* pw1      = (const float*)d_in[7];
    const float* g1       = (const float*)d_in[8];
    const float* b1       = (const float*)d_in[9];
    const float* dw2      = (const float*)d_in[10];
    const float* pw2      = (const float*)d_in[11];
    const float* g2       = (const float*)d_in[12];
    const float* b2       = (const float*)d_in[13];
    float* out = (float*)d_out;

    float *t1, *t2, *t3, *y0, *sumb, *sum2b;
    cudaGetSymbolAddress((void**)&t1, g_t1);
    cudaGetSymbolAddress((void**)&t2, g_t2);
    cudaGetSymbolAddress((void**)&t3, g_t3);
    cudaGetSymbolAddress((void**)&y0, g_y0);
    cudaGetSymbolAddress((void**)&sumb, g_sum);
    cudaGetSymbolAddress((void**)&sum2b, g_sum2);
    float* s0  = sumb;            float* q0 = sum2b;
    float* s1  = sumb + COUT;     float* q1 = sum2b + COUT;
    float* s2  = sumb + 2*COUT;   float* q2 = sum2b + 2*COUT;

    init_kernel<<<1, 128>>>();
    tab_kernel<<<(HW + 255) / 256, 256>>>(x_range);
    gather_kernel<<<dim3(HW / 64, CIN / 64), 256>>>(x, range_o);

    gemm_kernel<<<dim3(HW / 64, COUT / 64), 256>>>(w_reduce, y0, t1, CIN, s0, q0);
    dw_kernel<<<dim3((HW + 255) / 256, COUT), 256>>>(t1, dw1, t2, s0, q0, g_r, b_r);

    gemm_kernel<<<dim3(HW / 64, COUT / 64), 256>>>(pw1, t2, t3, COUT, s1, q1);
    dw_kernel<<<dim3((HW + 255) / 256, COUT), 256>>>(t3, dw2, t2, s1, q1, g1, b1);

    gemm_kernel<<<dim3(HW / 64, COUT / 64), 256>>>(pw2, t2, t1, COUT, s2, q2);
    apply_kernel<<<(COUT * HW / 4 + 255) / 256, 256>>>(t1, out, s2, q2, g2, b2);
}